// round 8
// baseline (speedup 1.0000x reference)
#include <cuda_runtime.h>
#include <cstdint>

#define NN      8192
#define THREADS 512
#define NCTA    148
#define WPC     (THREADS / 32)        // 16 warps per CTA
#define NWARPS  (NCTA * WPC)          // 2368 = 32 * 74
#define NSEG    32                    // column segments of 256 cols
#define SEGC    256
#define NRG     (NWARPS / NSEG)       // 74 rowgroups (~110 rows each)
#define RU      4                     // rows per block (12 values + 4 pad)
#define RBLKS   256                   // reduce grid

// scratch: __device__ globals (allocation-free rule). Every slot has exactly
// one unconditional writer per launch -> graph-replay deterministic.
__device__ float g_degpart[NWARPS * SEGC];      // 2.4 MB
__device__ float g_dotpart[NSEG * NN * 3];      // 3.1 MB
__device__ float g_losspart[RBLKS];

__device__ __forceinline__ float warp_sum(float v) {
    v += __shfl_down_sync(0xFFFFFFFFu, v, 16);
    v += __shfl_down_sync(0xFFFFFFFFu, v, 8);
    v += __shfl_down_sync(0xFFFFFFFFu, v, 4);
    v += __shfl_down_sync(0xFFFFFFFFu, v, 2);
    v += __shfl_down_sync(0xFFFFFFFFu, v, 1);
    return v;
}

// one butterfly step: live values v[0..L-1] -> v[0..L/2-1], width W
template <int L, int W>
__device__ __forceinline__ void bstep(float* v, int lane) {
    const int hi = lane & W;
    #pragma unroll
    for (int j = 0; j < L / 2; j++) {
        const float sent = hi ? v[j] : v[j + L / 2];
        const float got  = __shfl_xor_sync(0xFFFFFFFFu, sent, W);
        v[j] = (hi ? v[j + L / 2] : v[j]) + got;
    }
}

// load one block of RU rows (2 float4 per row) into buf
__device__ __forceinline__ void loadblk(float4 (&buf)[RU][2],
                                        const float4* __restrict__ Abase,
                                        int rbase, int stride4) {
    #pragma unroll
    for (int k = 0; k < RU; k++) {
        const float4* rp = Abase + (size_t)(rbase + k) * stride4;
        buf[k][0] = __ldcs(rp);
        buf[k][1] = __ldcs(rp + 1);
    }
}

// compute dots + deg for one block, butterfly-reduce, store 12 floats
__device__ __forceinline__ void compute_store(const float4 (&av)[RU][2],
                                              const float (&p)[8][3],
                                              float (&dg)[8],
                                              int lane, int seg, int grow) {
    float v[16];
    #pragma unroll
    for (int k = 0; k < RU; k++) {
        const float4 a0 = av[k][0], a1 = av[k][1];
        #pragma unroll
        for (int d = 0; d < 3; d++) {
            v[k * 3 + d] =
                a0.x * p[0][d] + a0.y * p[1][d] + a0.z * p[2][d] + a0.w * p[3][d] +
                a1.x * p[4][d] + a1.y * p[5][d] + a1.z * p[6][d] + a1.w * p[7][d];
        }
        dg[0] += a0.x; dg[1] += a0.y; dg[2] += a0.z; dg[3] += a0.w;
        dg[4] += a1.x; dg[5] += a1.y; dg[6] += a1.z; dg[7] += a1.w;
    }
    #pragma unroll
    for (int j = 12; j < 16; j++) v[j] = 0.0f;

    bstep<16, 16>(v, lane);
    bstep<8, 8>(v, lane);
    bstep<4, 4>(v, lane);
    bstep<2, 2>(v, lane);
    v[0] += __shfl_xor_sync(0xFFFFFFFFu, v[0], 1);

    const int k = lane >> 1;                       // value index 0..15
    if ((lane & 1) == 0 && k < 12)
        g_dotpart[((size_t)seg * NN + grow) * 3 + k] = v[0];
}

// ---------- kernel A: one streaming pass over A, software-pipelined ----------
__global__ void __launch_bounds__(THREADS, 1)
spmm_kernel(const float* __restrict__ pred1,
            const float* __restrict__ pred2,
            const float* __restrict__ A) {
    const int tid  = threadIdx.x;
    const int lane = tid & 31;
    const int warp = tid >> 5;

    const int w    = blockIdx.x * WPC + warp;
    const int seg  = w & (NSEG - 1);
    const int rg   = w >> 5;
    const int col0 = seg * SEGC + lane * 8;        // this lane's 8 columns
    const int r0   = (rg * NN) / NRG;
    const int r1   = ((rg + 1) * NN) / NRG;

    // hoist p = pred2 - pred1 for this lane's 8 columns: p[jc][d], 24 regs
    float p[8][3];
    {
        const float4* q1 = reinterpret_cast<const float4*>(pred1 + (size_t)col0 * 3);
        const float4* q2 = reinterpret_cast<const float4*>(pred2 + (size_t)col0 * 3);
        float tmp[24];
        #pragma unroll
        for (int k = 0; k < 6; k++) {
            const float4 a = q2[k];
            const float4 b = q1[k];
            tmp[4 * k + 0] = a.x - b.x;
            tmp[4 * k + 1] = a.y - b.y;
            tmp[4 * k + 2] = a.z - b.z;
            tmp[4 * k + 3] = a.w - b.w;
        }
        #pragma unroll
        for (int j = 0; j < 24; j++) p[j / 3][j % 3] = tmp[j];
    }

    float dg[8];
    #pragma unroll
    for (int j = 0; j < 8; j++) dg[j] = 0.0f;

    const float4* __restrict__ Abase =
        reinterpret_cast<const float4*>(A + (size_t)r0 * NN + col0);
    const int stride4 = NN / 4;
    const int rows = r1 - r0;
    const int nblk = rows / RU;

    float4 bufA[RU][2], bufB[RU][2];
    if (nblk > 0) loadblk(bufA, Abase, 0, stride4);

    int b = 0;
    for (; b + 2 <= nblk; b += 2) {
        loadblk(bufB, Abase, (b + 1) * RU, stride4);
        compute_store(bufA, p, dg, lane, seg, r0 + b * RU);
        if (b + 2 < nblk) loadblk(bufA, Abase, (b + 2) * RU, stride4);
        compute_store(bufB, p, dg, lane, seg, r0 + (b + 1) * RU);
    }
    if (b < nblk) {                                // odd nblk: bufA holds block b
        compute_store(bufA, p, dg, lane, seg, r0 + b * RU);
        b++;
    }

    // tail rows (< RU): plain warp reduction
    for (int r = nblk * RU; r < rows; r++) {
        const float4* rp = Abase + (size_t)r * stride4;
        const float4 a0 = __ldcs(rp);
        const float4 a1 = __ldcs(rp + 1);
        float t[3];
        #pragma unroll
        for (int d = 0; d < 3; d++) {
            t[d] = warp_sum(
                a0.x * p[0][d] + a0.y * p[1][d] + a0.z * p[2][d] + a0.w * p[3][d] +
                a1.x * p[4][d] + a1.y * p[5][d] + a1.z * p[6][d] + a1.w * p[7][d]);
        }
        dg[0] += a0.x; dg[1] += a0.y; dg[2] += a0.z; dg[3] += a0.w;
        dg[4] += a1.x; dg[5] += a1.y; dg[6] += a1.z; dg[7] += a1.w;
        if (lane == 0) {
            float* dst = g_dotpart + ((size_t)seg * NN + (r0 + r)) * 3;
            dst[0] = t[0]; dst[1] = t[1]; dst[2] = t[2];
        }
    }

    // flush deg partials for this warp's 256 columns (2 float4 per lane)
    {
        float* dst = g_degpart + (size_t)w * SEGC + lane * 8;
        float4 d0; d0.x = dg[0]; d0.y = dg[1]; d0.z = dg[2]; d0.w = dg[3];
        float4 d1; d1.x = dg[4]; d1.y = dg[5]; d1.z = dg[6]; d1.w = dg[7];
        *reinterpret_cast<float4*>(dst)     = d0;
        *reinterpret_cast<float4*>(dst + 4) = d1;
    }
}

// ---------- kernel B: reduce partials, 8 threads per node ----------
__global__ void __launch_bounds__(256)
reduce_kernel(const float* __restrict__ pred1,
              const float* __restrict__ pred2) {
    __shared__ float red[8];
    const int tid  = threadIdx.x;
    const int lane = tid & 31;
    const int warp = tid >> 5;
    const int g    = blockIdx.x * 256 + tid;       // 256*256 = 65536 = 8192*8
    const int i    = g >> 3;                       // node id
    const int j    = g & 7;                        // sub-thread

    // deg(i): sub j sums rowgroups j, j+8, ... (~9 each)
    const int seg = i >> 8;
    const int c   = i & (SEGC - 1);
    float deg = 0.0f;
    for (int rg = j; rg < NRG; rg += 8)
        deg += g_degpart[((size_t)rg * NSEG + seg) * SEGC + c];

    // dot(i): sub j sums segments j, j+8, ... (4 each)
    float t0 = 0.0f, t1 = 0.0f, t2 = 0.0f;
    #pragma unroll
    for (int s = j; s < NSEG; s += 8) {
        const float* q = g_dotpart + ((size_t)s * NN + i) * 3;
        t0 += q[0]; t1 += q[1]; t2 += q[2];
    }

    // combine the 8 sub-threads (lanes 8k..8k+7 hold node k's partials)
    #pragma unroll
    for (int m = 1; m <= 4; m <<= 1) {
        deg += __shfl_xor_sync(0xFFFFFFFFu, deg, m);
        t0  += __shfl_xor_sync(0xFFFFFFFFu, t0, m);
        t1  += __shfl_xor_sync(0xFFFFFFFFu, t1, m);
        t2  += __shfl_xor_sync(0xFFFFFFFFu, t2, m);
    }

    float s = 0.0f;
    if (j == 0) {
        const float inv = 1.0f / deg;
        const float p0 = pred2[3 * i + 0] - pred1[3 * i + 0];
        const float p1 = pred2[3 * i + 1] - pred1[3 * i + 1];
        const float p2 = pred2[3 * i + 2] - pred1[3 * i + 2];
        const float e0 = p0 - t0 * inv;
        const float e1 = p1 - t1 * inv;
        const float e2 = p2 - t2 * inv;
        s = e0 * e0 + e1 * e1 + e2 * e2;
    }

    s = warp_sum(s);
    if (lane == 0) red[warp] = s;
    __syncthreads();
    if (tid == 0) {
        float v = 0.0f;
        #pragma unroll
        for (int k = 0; k < 8; k++) v += red[k];
        g_losspart[blockIdx.x] = v;
    }
}

// ---------- kernel C: final scalar ----------
__global__ void final_kernel(float* __restrict__ out) {
    __shared__ float red[8];
    const int tid  = threadIdx.x;                  // 256 threads
    const int lane = tid & 31;
    const int warp = tid >> 5;
    float v = warp_sum(g_losspart[tid]);
    if (lane == 0) red[warp] = v;
    __syncthreads();
    if (tid == 0) {
        float t = 0.0f;
        #pragma unroll
        for (int k = 0; k < 8; k++) t += red[k];
        out[0] = t;
    }
}

extern "C" void kernel_launch(void* const* d_in, const int* in_sizes, int n_in,
                              void* d_out, int out_size) {
    const float* pred1 = (const float*)d_in[0];
    const float* pred2 = (const float*)d_in[1];
    const float* A     = (const float*)d_in[2];
    float* out = (float*)d_out;

    spmm_kernel<<<NCTA, THREADS>>>(pred1, pred2, A);
    reduce_kernel<<<RBLKS, 256>>>(pred1, pred2);
    final_kernel<<<1, RBLKS>>>(out);
}

// round 9
// speedup vs baseline: 1.0069x; 1.0069x over previous
#include <cuda_runtime.h>
#include <cstdint>

#define NN      8192
#define THREADS 640                   // 20 warps per CTA
#define NCTA    148
#define WPC     (THREADS / 32)        // 20
#define NWARPS  (NCTA * WPC)          // 2960
#define NSEG    32                    // column segments of 256 cols
#define SEGC    256
#define NRG     92                    // rowgroups (32*92 = 2944 working warps)
#define RU      5                     // rows per inner iteration (15 values + pad)
#define RBLKS   256                   // reduce grid

// scratch: __device__ globals (allocation-free rule). Every read slot has
// exactly one unconditional writer per launch -> graph-replay deterministic.
__device__ float g_degpart[NWARPS * SEGC];      // 2.9 MB (only first 2944 rows read)
__device__ float g_dotpart[NSEG * NN * 3];      // 3.1 MB
__device__ float g_losspart[RBLKS];
__device__ int   g_done;                        // reset by unique last block

__device__ __forceinline__ float warp_sum(float v) {
    v += __shfl_down_sync(0xFFFFFFFFu, v, 16);
    v += __shfl_down_sync(0xFFFFFFFFu, v, 8);
    v += __shfl_down_sync(0xFFFFFFFFu, v, 4);
    v += __shfl_down_sync(0xFFFFFFFFu, v, 2);
    v += __shfl_down_sync(0xFFFFFFFFu, v, 1);
    return v;
}

// one butterfly step: live values v[0..L-1] -> v[0..L/2-1], width W
template <int L, int W>
__device__ __forceinline__ void bstep(float* v, int lane) {
    const int hi = lane & W;
    #pragma unroll
    for (int j = 0; j < L / 2; j++) {
        const float sent = hi ? v[j] : v[j + L / 2];
        const float got  = __shfl_xor_sync(0xFFFFFFFFu, sent, W);
        v[j] = (hi ? v[j + L / 2] : v[j]) + got;
    }
}

// ---------- kernel A: one streaming pass over A ----------
__global__ void __launch_bounds__(THREADS, 1)
spmm_kernel(const float* __restrict__ pred1,
            const float* __restrict__ pred2,
            const float* __restrict__ A) {
    const int tid  = threadIdx.x;
    const int lane = tid & 31;
    const int warp = tid >> 5;

    const int w    = blockIdx.x * WPC + warp;
    const int seg  = w & (NSEG - 1);
    const int rg   = w >> 5;
    const int col0 = seg * SEGC + lane * 8;        // this lane's 8 columns
    const bool active = (rg < NRG);
    const int r0   = active ? (rg * NN) / NRG : 0;
    const int r1   = active ? ((rg + 1) * NN) / NRG : 0;

    // hoist p = pred2 - pred1 for this lane's 8 columns: p[jc][d], 24 regs
    float p[8][3];
    {
        const float4* q1 = reinterpret_cast<const float4*>(pred1 + (size_t)col0 * 3);
        const float4* q2 = reinterpret_cast<const float4*>(pred2 + (size_t)col0 * 3);
        float tmp[24];
        #pragma unroll
        for (int k = 0; k < 6; k++) {
            const float4 a = q2[k];
            const float4 b = q1[k];
            tmp[4 * k + 0] = a.x - b.x;
            tmp[4 * k + 1] = a.y - b.y;
            tmp[4 * k + 2] = a.z - b.z;
            tmp[4 * k + 3] = a.w - b.w;
        }
        #pragma unroll
        for (int j = 0; j < 24; j++) p[j / 3][j % 3] = tmp[j];
    }

    float dg[8];
    #pragma unroll
    for (int j = 0; j < 8; j++) dg[j] = 0.0f;

    const float4* __restrict__ Abase =
        reinterpret_cast<const float4*>(A + (size_t)r0 * NN + col0);
    const int stride4 = NN / 4;
    const int rows = r1 - r0;

    int r = 0;
    for (; r + RU <= rows; r += RU) {
        // front-batch 2*RU = 10 independent loads
        float4 av[RU][2];
        #pragma unroll
        for (int k = 0; k < RU; k++) {
            const float4* rp = Abase + (size_t)(r + k) * stride4;
            av[k][0] = __ldcs(rp);
            av[k][1] = __ldcs(rp + 1);
        }

        float v[16];
        #pragma unroll
        for (int k = 0; k < RU; k++) {
            const float4 a0 = av[k][0], a1 = av[k][1];
            #pragma unroll
            for (int d = 0; d < 3; d++) {
                v[k * 3 + d] =
                    a0.x * p[0][d] + a0.y * p[1][d] + a0.z * p[2][d] + a0.w * p[3][d] +
                    a1.x * p[4][d] + a1.y * p[5][d] + a1.z * p[6][d] + a1.w * p[7][d];
            }
            dg[0] += a0.x; dg[1] += a0.y; dg[2] += a0.z; dg[3] += a0.w;
            dg[4] += a1.x; dg[5] += a1.y; dg[6] += a1.z; dg[7] += a1.w;
        }
        v[15] = 0.0f;                              // pad to 16

        // multi-value butterfly: after 5 steps, lane pair floor(l/2)
        // holds the full 32-lane sum of value floor(l/2)
        bstep<16, 16>(v, lane);
        bstep<8, 8>(v, lane);
        bstep<4, 4>(v, lane);
        bstep<2, 2>(v, lane);
        v[0] += __shfl_xor_sync(0xFFFFFFFFu, v[0], 1);

        const int k = lane >> 1;                   // value index 0..15
        if ((lane & 1) == 0 && k < 15)
            g_dotpart[((size_t)seg * NN + (r0 + r)) * 3 + k] = v[0];
    }

    // tail rows (<= RU-1): plain warp reduction
    for (; r < rows; r++) {
        const float4* rp = Abase + (size_t)r * stride4;
        const float4 a0 = __ldcs(rp);
        const float4 a1 = __ldcs(rp + 1);
        float t[3];
        #pragma unroll
        for (int d = 0; d < 3; d++) {
            t[d] = warp_sum(
                a0.x * p[0][d] + a0.y * p[1][d] + a0.z * p[2][d] + a0.w * p[3][d] +
                a1.x * p[4][d] + a1.y * p[5][d] + a1.z * p[6][d] + a1.w * p[7][d]);
        }
        dg[0] += a0.x; dg[1] += a0.y; dg[2] += a0.z; dg[3] += a0.w;
        dg[4] += a1.x; dg[5] += a1.y; dg[6] += a1.z; dg[7] += a1.w;
        if (lane == 0) {
            float* dst = g_dotpart + ((size_t)seg * NN + (r0 + r)) * 3;
            dst[0] = t[0]; dst[1] = t[1]; dst[2] = t[2];
        }
    }

    // flush deg partials (inactive warps write zeros to their own unread slot)
    {
        float* dst = g_degpart + (size_t)w * SEGC + lane * 8;
        float4 d0; d0.x = dg[0]; d0.y = dg[1]; d0.z = dg[2]; d0.w = dg[3];
        float4 d1; d1.x = dg[4]; d1.y = dg[5]; d1.z = dg[6]; d1.w = dg[7];
        *reinterpret_cast<float4*>(dst)     = d0;
        *reinterpret_cast<float4*>(dst + 4) = d1;
    }
}

// ---------- kernel B: reduce partials (8 threads/node) + fused final ----------
__global__ void __launch_bounds__(256)
reduce_kernel(const float* __restrict__ pred1,
              const float* __restrict__ pred2,
              float* __restrict__ out) {
    __shared__ float red[8];
    __shared__ int  isLast;
    const int tid  = threadIdx.x;
    const int lane = tid & 31;
    const int warp = tid >> 5;
    const int g    = blockIdx.x * 256 + tid;       // 256*256 = 65536 = 8192*8
    const int i    = g >> 3;                       // node id
    const int j    = g & 7;                        // sub-thread

    // deg(i): sub j sums rowgroups j, j+8, ... (~12 each)
    const int seg = i >> 8;
    const int c   = i & (SEGC - 1);
    float deg = 0.0f;
    for (int rg = j; rg < NRG; rg += 8)
        deg += g_degpart[((size_t)rg * NSEG + seg) * SEGC + c];

    // dot(i): sub j sums segments j, j+8, ... (4 each)
    float t0 = 0.0f, t1 = 0.0f, t2 = 0.0f;
    #pragma unroll
    for (int s = j; s < NSEG; s += 8) {
        const float* q = g_dotpart + ((size_t)s * NN + i) * 3;
        t0 += q[0]; t1 += q[1]; t2 += q[2];
    }

    // combine the 8 sub-threads (lanes 8k..8k+7 hold node k's partials)
    #pragma unroll
    for (int m = 1; m <= 4; m <<= 1) {
        deg += __shfl_xor_sync(0xFFFFFFFFu, deg, m);
        t0  += __shfl_xor_sync(0xFFFFFFFFu, t0, m);
        t1  += __shfl_xor_sync(0xFFFFFFFFu, t1, m);
        t2  += __shfl_xor_sync(0xFFFFFFFFu, t2, m);
    }

    float s = 0.0f;
    if (j == 0) {
        const float inv = 1.0f / deg;
        const float p0 = pred2[3 * i + 0] - pred1[3 * i + 0];
        const float p1 = pred2[3 * i + 1] - pred1[3 * i + 1];
        const float p2 = pred2[3 * i + 2] - pred1[3 * i + 2];
        const float e0 = p0 - t0 * inv;
        const float e1 = p1 - t1 * inv;
        const float e2 = p2 - t2 * inv;
        s = e0 * e0 + e1 * e1 + e2 * e2;
    }

    s = warp_sum(s);
    if (lane == 0) red[warp] = s;
    __syncthreads();
    if (tid == 0) {
        float v = 0.0f;
        #pragma unroll
        for (int k = 0; k < 8; k++) v += red[k];
        g_losspart[blockIdx.x] = v;
        __threadfence();
        isLast = (atomicAdd(&g_done, 1) == RBLKS - 1);
    }
    __syncthreads();

    if (isLast) {
        __threadfence();
        float v = warp_sum(__ldcg(&g_losspart[tid]));
        if (lane == 0) red[warp] = v;
        __syncthreads();
        if (tid == 0) {
            float t = 0.0f;
            #pragma unroll
            for (int k = 0; k < 8; k++) t += red[k];
            out[0] = t;
            g_done = 0;                            // reset for next graph replay
        }
    }
}

extern "C" void kernel_launch(void* const* d_in, const int* in_sizes, int n_in,
                              void* d_out, int out_size) {
    const float* pred1 = (const float*)d_in[0];
    const float* pred2 = (const float*)d_in[1];
    const float* A     = (const float*)d_in[2];
    float* out = (float*)d_out;

    spmm_kernel<<<NCTA, THREADS>>>(pred1, pred2, A);
    reduce_kernel<<<RBLKS, 256>>>(pred1, pred2, out);
}